// round 6
// baseline (speedup 1.0000x reference)
#include <cuda_runtime.h>
#include <cuda_fp16.h>
#include <math.h>
#include <stdint.h>

#define N_TOK 4096
#define D_DIM 1024
#define H_DIM 2048
#define E_NUM 8
#define NASG  (N_TOK * 2)

#define BM 128
#define BN 256
#define NSTAGE 3
#define TILE_A 16384                          // 128 rows x 128B
#define TILE_B 32768                          // 256 rows x 128B
#define STAGE_BYTES (TILE_A + TILE_B)         // 48KB
#define SMEM_DYN (1024 + 2048 + NSTAGE * STAGE_BYTES)   // ~150KB -> 1 CTA/SM

// ---------------- device scratch ----------------
__device__ int   g_cnt[E_NUM];
__device__ int   g_asg[E_NUM][N_TOK];
__device__ float g_gate[E_NUM][N_TOK];

__device__ __align__(256) __half g_xh[(size_t)N_TOK * D_DIM];
__device__ __align__(256) __half g_w1h[(size_t)E_NUM * H_DIM * D_DIM];
__device__ __align__(256) __half g_w2h[(size_t)E_NUM * D_DIM * H_DIM];
__device__ __align__(256) __half g_hh[(size_t)NASG * H_DIM];

// ---------------- helpers ----------------
__device__ __forceinline__ uint32_t smem_u32(const void* p) {
    uint32_t a;
    asm("{ .reg .u64 t; cvta.to.shared.u64 t, %1; cvt.u32.u64 %0, t; }" : "=r"(a) : "l"(p));
    return a;
}
#define SW128(o) ((o) ^ (((o) >> 3) & 0x70))

#define CP16(dst, src) asm volatile("cp.async.cg.shared.global [%0], [%1], 16;" :: "r"(dst), "l"(src))
#define CP_COMMIT()    asm volatile("cp.async.commit_group;" ::: "memory")
#define CP_WAIT1()     asm volatile("cp.async.wait_group 1;" ::: "memory")
#define CP_WAIT0()     asm volatile("cp.async.wait_group 0;" ::: "memory")

#define LDSM4(r0, r1, r2, r3, addr)                                             \
    asm volatile("ldmatrix.sync.aligned.m8n8.x4.shared.b16 {%0,%1,%2,%3}, [%4];" \
        : "=r"(r0), "=r"(r1), "=r"(r2), "=r"(r3) : "r"(addr))

#define MMA16816(d, a0, a1, a2, a3, b0, b1)                                     \
    asm volatile("mma.sync.aligned.m16n8k16.row.col.f32.f16.f16.f32 "           \
        "{%0,%1,%2,%3}, {%4,%5,%6,%7}, {%8,%9}, {%0,%1,%2,%3};"                 \
        : "+f"((d)[0]), "+f"((d)[1]), "+f"((d)[2]), "+f"((d)[3])                \
        : "r"(a0), "r"(a1), "r"(a2), "r"(a3), "r"(b0), "r"(b1))

// ---------------- small kernels ----------------
__global__ void init_kernel() {
    if (threadIdx.x < E_NUM) g_cnt[threadIdx.x] = 0;
}

__global__ void gating_kernel(const float* __restrict__ x, const float* __restrict__ gw) {
    int tok  = (blockIdx.x * blockDim.x + threadIdx.x) >> 5;
    int lane = threadIdx.x & 31;
    if (tok >= N_TOK) return;
    const float* xr = x + (size_t)tok * D_DIM;
    float acc[E_NUM];
#pragma unroll
    for (int e = 0; e < E_NUM; e++) acc[e] = 0.f;
    for (int d = lane; d < D_DIM; d += 32) {
        float xv = xr[d];
#pragma unroll
        for (int e = 0; e < E_NUM; e++)
            acc[e] = fmaf(xv, __ldg(gw + (size_t)e * D_DIM + d), acc[e]);
    }
#pragma unroll
    for (int e = 0; e < E_NUM; e++) {
#pragma unroll
        for (int off = 16; off > 0; off >>= 1)
            acc[e] += __shfl_xor_sync(0xffffffffu, acc[e], off);
    }
    if (lane == 0) {
        int i0 = 0; float v0 = acc[0];
#pragma unroll
        for (int e = 1; e < E_NUM; e++)
            if (acc[e] > v0) { v0 = acc[e]; i0 = e; }
        int i1 = -1; float v1 = -3.4e38f;
#pragma unroll
        for (int e = 0; e < E_NUM; e++)
            if (e != i0 && acc[e] > v1) { v1 = acc[e]; i1 = e; }
        float ex = expf(v1 - v0);
        float s  = 1.f + ex;
        int p0 = atomicAdd(&g_cnt[i0], 1);
        g_asg[i0][p0]  = (tok << 1);
        g_gate[i0][p0] = 1.f / s;
        int p1 = atomicAdd(&g_cnt[i1], 1);
        g_asg[i1][p1]  = (tok << 1) | 1;
        g_gate[i1][p1] = ex / s;
    }
}

__global__ void aux_kernel(float* __restrict__ out_aux) {
    float s = 0.f;
#pragma unroll
    for (int e = 0; e < E_NUM; e++) {
        float load = (float)g_cnt[e] / (float)(N_TOK * 2);
        s += load * load;
    }
    *out_aux = 0.01f * (float)E_NUM * s;
}

// convert x, w1, w2 to fp16; 4-way ILP grid-stride
#define NX4  (N_TOK * D_DIM / 4)
#define NW14 (E_NUM * H_DIM * D_DIM / 4)
#define NW24 (E_NUM * D_DIM * H_DIM / 4)
#define NTOT4 (NX4 + NW14 + NW24)
__global__ void split_all_kernel(const float4* __restrict__ x,
                                 const float4* __restrict__ w1,
                                 const float4* __restrict__ w2) {
    int stride = gridDim.x * blockDim.x;
    int i0 = blockIdx.x * blockDim.x + threadIdx.x;
#pragma unroll 4
    for (int u = 0; u < 4; u++) {
        int i = i0 + u * stride;
        if (i >= NTOT4) break;
        const float4* src;
        uint2* dst;
        int j;
        if (i < NX4)              { src = x;  j = i;               dst = (uint2*)g_xh; }
        else if (i < NX4 + NW14)  { src = w1; j = i - NX4;         dst = (uint2*)g_w1h; }
        else                      { src = w2; j = i - NX4 - NW14;  dst = (uint2*)g_w2h; }
        float4 v = src[j];
        __half2 lo = __floats2half2_rn(v.x, v.y);
        __half2 hi = __floats2half2_rn(v.z, v.w);
        dst[j] = make_uint2(*(uint32_t*)&lo, *(uint32_t*)&hi);
    }
}

// ---------------- HMMA mainloop: 128x256 CTA tile, 8 warps of 64x64 ----------------
// A tile: 128 rows x 128B (gathered tokens), B tile: 256 rows x 128B (weight rows)
#define GEMM_MAINLOOP(KDIM, SRC_A, SRC_B)                                          \
    const int C = (KDIM) / 64;                                                     \
    const char* srcA = SRC_A;                                                      \
    const char* srcB = SRC_B;                                                      \
    uint32_t dstA[4], dstB[8];                                                     \
    {                                                                              \
        uint32_t rowA = tid >> 1, colA = (tid & 1) * 4;                            \
        _Pragma("unroll")                                                          \
        for (int t = 0; t < 4; t++)                                                \
            dstA[t] = SW128((uint32_t)(rowA * 128 + (colA + t) * 16));             \
        _Pragma("unroll")                                                          \
        for (int t = 0; t < 8; t++)                                                \
            dstB[t] = TILE_A + SW128((uint32_t)(tid * 128 + t * 16));              \
    }                                                                              \
    _Pragma("unroll")                                                              \
    for (int c = 0; c < 2; c++) {                                                  \
        uint32_t sb = ub + c * STAGE_BYTES;                                        \
        size_t ko = (size_t)c * 128;                                               \
        _Pragma("unroll")                                                          \
        for (int t = 0; t < 4; t++) CP16(sb + dstA[t], srcA + ko + t * 16);        \
        _Pragma("unroll")                                                          \
        for (int t = 0; t < 8; t++) CP16(sb + dstB[t], srcB + ko + t * 16);        \
        CP_COMMIT();                                                               \
    }                                                                              \
    const int wm = (wid & 1) * 64;                                                 \
    const int wn = (wid >> 1) * 64;                                                \
    uint32_t aoffs[4], boffs[4];                                                   \
    _Pragma("unroll")                                                              \
    for (int mi = 0; mi < 4; mi++)                                                 \
        aoffs[mi] = SW128((uint32_t)((wm + mi * 16 + (lane & 15)) * 128            \
                                     + (lane >> 4) * 16));                         \
    _Pragma("unroll")                                                              \
    for (int nq = 0; nq < 4; nq++)                                                 \
        boffs[nq] = TILE_A + SW128((uint32_t)((wn + nq * 16 + (lane & 15)) * 128   \
                                              + (lane >> 4) * 16));                \
    float acc[4][8][4];                                                            \
    _Pragma("unroll")                                                              \
    for (int i = 0; i < 4; i++)                                                    \
        _Pragma("unroll")                                                          \
        for (int j = 0; j < 8; j++)                                                \
            _Pragma("unroll")                                                      \
            for (int q = 0; q < 4; q++) acc[i][j][q] = 0.f;                        \
    for (int c = 0; c < C; c++) {                                                  \
        if (c >= C - 2) { CP_WAIT0(); } else { CP_WAIT1(); }                       \
        __syncthreads();                                                           \
        int cn = c + 2;                                                            \
        if (cn < C) {                                                              \
            uint32_t sb = ub + (cn % NSTAGE) * STAGE_BYTES;                        \
            size_t ko = (size_t)cn * 128;                                          \
            _Pragma("unroll")                                                      \
            for (int t = 0; t < 4; t++) CP16(sb + dstA[t], srcA + ko + t * 16);    \
            _Pragma("unroll")                                                      \
            for (int t = 0; t < 8; t++) CP16(sb + dstB[t], srcB + ko + t * 16);    \
            CP_COMMIT();                                                           \
        }                                                                          \
        uint32_t sbase = ub + (c % NSTAGE) * STAGE_BYTES;                          \
        _Pragma("unroll")                                                          \
        for (int kk = 0; kk < 4; kk++) {                                           \
            uint32_t a[4][4], b[4][4];                                             \
            _Pragma("unroll")                                                      \
            for (int mi = 0; mi < 4; mi++)                                         \
                LDSM4(a[mi][0], a[mi][1], a[mi][2], a[mi][3],                      \
                      sbase + (aoffs[mi] ^ (kk * 32)));                            \
            _Pragma("unroll")                                                      \
            for (int nq = 0; nq < 4; nq++)                                         \
                LDSM4(b[nq][0], b[nq][1], b[nq][2], b[nq][3],                      \
                      sbase + (boffs[nq] ^ (kk * 32)));                            \
            _Pragma("unroll")                                                      \
            for (int mi = 0; mi < 4; mi++)                                         \
                _Pragma("unroll")                                                  \
                for (int nq = 0; nq < 4; nq++) {                                   \
                    MMA16816(acc[mi][nq * 2],     a[mi][0], a[mi][1], a[mi][2],    \
                             a[mi][3], b[nq][0], b[nq][2]);                        \
                    MMA16816(acc[mi][nq * 2 + 1], a[mi][0], a[mi][1], a[mi][2],    \
                             a[mi][3], b[nq][1], b[nq][3]);                        \
                }                                                                  \
        }                                                                          \
    }

// GEMM1: h[aid] = silu(x[tok] @ w1[e]^T + b1[e]) -> fp16
__global__ __launch_bounds__(256) void gemm1_mma(const float* __restrict__ b1) {
    const int e   = blockIdx.z;
    const int cnt = g_cnt[e];
    const int m0  = blockIdx.x * BM;
    if (m0 >= cnt) return;
    const int n0  = blockIdx.y * BN;

    extern __shared__ char dsm[];
    char* base = (char*)(((uintptr_t)dsm + 1023) & ~(uintptr_t)1023);
    int* sAsg = (int*)base;
    uint32_t ub = smem_u32(base) + 2048;

    const int tid = threadIdx.x, wid = tid >> 5, lane = tid & 31;
    if (tid < BM) {
        int r = m0 + tid;
        sAsg[tid] = (r < cnt) ? g_asg[e][r] : -1;
    }
    __syncthreads();

    int aidL = sAsg[tid >> 1];
    int tokL = (aidL >= 0) ? (aidL >> 1) : 0;
    size_t aoff = ((size_t)tokL * D_DIM + (size_t)(tid & 1) * 32) * 2;
    size_t boff = (((size_t)e * H_DIM + n0 + tid) * D_DIM) * 2;

    GEMM_MAINLOOP(D_DIM,
        (const char*)g_xh + aoff,
        (const char*)g_w1h + boff)

    const float* b1e = b1 + (size_t)e * H_DIM + n0;
    float bias[8][2];
#pragma unroll
    for (int j = 0; j < 8; j++) {
        int cb = wn + (j >> 1) * 16 + (j & 1) * 8 + (lane & 3) * 2;
        bias[j][0] = __ldg(b1e + cb);
        bias[j][1] = __ldg(b1e + cb + 1);
    }
#pragma unroll
    for (int mi = 0; mi < 4; mi++) {
#pragma unroll
        for (int h = 0; h < 2; h++) {
            int row = wm + mi * 16 + (lane >> 2) + h * 8;
            int aid = sAsg[row];
            if (aid < 0) continue;
            __half* hh = g_hh + (size_t)aid * H_DIM + n0;
#pragma unroll
            for (int j = 0; j < 8; j++) {
                int cb = wn + (j >> 1) * 16 + (j & 1) * 8 + (lane & 3) * 2;
                float v0 = acc[mi][j][h * 2]     + bias[j][0];
                float v1 = acc[mi][j][h * 2 + 1] + bias[j][1];
                v0 = v0 / (1.f + __expf(-v0));
                v1 = v1 / (1.f + __expf(-v1));
                __half2 p = __floats2half2_rn(v0, v1);
                *(uint32_t*)(hh + cb) = *(uint32_t*)&p;
            }
        }
    }
}

// GEMM2: out[tok] += gate * ( h[aid] @ w2[e]^T + b2[e] )
__global__ __launch_bounds__(256) void gemm2_mma(const float* __restrict__ b2,
                                                 float* __restrict__ out) {
    const int e   = blockIdx.z;
    const int cnt = g_cnt[e];
    const int m0  = blockIdx.x * BM;
    if (m0 >= cnt) return;
    const int n0  = blockIdx.y * BN;

    extern __shared__ char dsm[];
    char* base = (char*)(((uintptr_t)dsm + 1023) & ~(uintptr_t)1023);
    int*   sAsg  = (int*)base;
    float* sGate = (float*)(base + 512);
    uint32_t ub = smem_u32(base) + 2048;

    const int tid = threadIdx.x, wid = tid >> 5, lane = tid & 31;
    if (tid < BM) {
        int r = m0 + tid;
        sAsg[tid]  = (r < cnt) ? g_asg[e][r] : -1;
        sGate[tid] = (r < cnt) ? g_gate[e][r] : 0.f;
    }
    __syncthreads();

    int aidL = sAsg[tid >> 1];
    int arwL = (aidL >= 0) ? aidL : 0;
    size_t aoff = ((size_t)arwL * H_DIM + (size_t)(tid & 1) * 32) * 2;
    size_t boff = (((size_t)e * D_DIM + n0 + tid) * H_DIM) * 2;

    GEMM_MAINLOOP(H_DIM,
        (const char*)g_hh + aoff,
        (const char*)g_w2h + boff)

    const float* b2e = b2 + (size_t)e * D_DIM + n0;
    float bias[8][2];
#pragma unroll
    for (int j = 0; j < 8; j++) {
        int cb = wn + (j >> 1) * 16 + (j & 1) * 8 + (lane & 3) * 2;
        bias[j][0] = __ldg(b2e + cb);
        bias[j][1] = __ldg(b2e + cb + 1);
    }
#pragma unroll
    for (int mi = 0; mi < 4; mi++) {
#pragma unroll
        for (int h = 0; h < 2; h++) {
            int row = wm + mi * 16 + (lane >> 2) + h * 8;
            int aid = sAsg[row];
            if (aid < 0) continue;
            float gte = sGate[row];
            float* orow = out + (size_t)(aid >> 1) * D_DIM + n0;
#pragma unroll
            for (int j = 0; j < 8; j++) {
                int cb = wn + (j >> 1) * 16 + (j & 1) * 8 + (lane & 3) * 2;
                atomicAdd(orow + cb,     gte * (acc[mi][j][h * 2]     + bias[j][0]));
                atomicAdd(orow + cb + 1, gte * (acc[mi][j][h * 2 + 1] + bias[j][1]));
            }
        }
    }
}

// ---------------- launch ----------------
extern "C" void kernel_launch(void* const* d_in, const int* in_sizes, int n_in,
                              void* d_out, int out_size) {
    const float* x  = (const float*)d_in[0];
    const float* gw = (const float*)d_in[1];
    const float* w1 = (const float*)d_in[2];
    const float* b1 = (const float*)d_in[3];
    const float* w2 = (const float*)d_in[4];
    const float* b2 = (const float*)d_in[5];
    float* out = (float*)d_out;

    cudaFuncSetAttribute(gemm1_mma, cudaFuncAttributeMaxDynamicSharedMemorySize, SMEM_DYN);
    cudaFuncSetAttribute(gemm2_mma, cudaFuncAttributeMaxDynamicSharedMemorySize, SMEM_DYN);

    cudaMemsetAsync(out, 0, (size_t)N_TOK * D_DIM * sizeof(float), 0);

    init_kernel<<<1, 32>>>();
    gating_kernel<<<N_TOK / 8, 256>>>(x, gw);

    int nblk = (NTOT4 / 4 + 255) / 256;
    split_all_kernel<<<nblk, 256>>>((const float4*)x, (const float4*)w1, (const float4*)w2);

    // gemm1 in the ncu capture window
    dim3 g1(N_TOK / BM, H_DIM / BN, E_NUM);   // (32, 8, 8)
    gemm1_mma<<<g1, 256, SMEM_DYN>>>(b1);

    dim3 g2(N_TOK / BM, D_DIM / BN, E_NUM);   // (32, 4, 8)
    gemm2_mma<<<g2, 256, SMEM_DYN>>>(b2, out);

    aux_kernel<<<1, 1>>>(out + (out_size - 1));
}